// round 3
// baseline (speedup 1.0000x reference)
#include <cuda_runtime.h>

// Net_90434831385322: z = LIM_A + span*sigmoid( relu(((x-LIM_A)/span) @ W1 + b1) @ W2 + b2 )
//
// R3 design:
//  - Input scaling folded into W1/b1.
//  - Layer2 fused into hidden-unit stream loop (no h[] array).
//  - ALL packed f32x2 values carried as u64 registers end-to-end; weights stored
//    in shared as pre-duplicated u64 pairs -> fma.rn.f32x2 operands need no
//    pack/unpack MOVs (R2's alu-pipe flood).
//  - 4 rows per thread (2 row-pairs per f32x2 lane dimension).

typedef unsigned long long u64;

__device__ __forceinline__ u64 ffma2(u64 a, u64 b, u64 c) {
    u64 d;
    asm("fma.rn.f32x2 %0, %1, %2, %3;" : "=l"(d) : "l"(a), "l"(b), "l"(c));
    return d;
}

__device__ __forceinline__ u64 pack2(float lo, float hi) {
    u64 d;
    asm("mov.b64 %0, {%1, %2};" : "=l"(d) : "f"(lo), "f"(hi));
    return d;
}

__device__ __forceinline__ void unpack2(u64 v, float& lo, float& hi) {
    asm("mov.b64 {%0, %1}, %2;" : "=f"(lo), "=f"(hi) : "l"(v));
}

__device__ __forceinline__ u64 relu2(u64 h) {
    float a, b;
    unpack2(h, a, b);
    a = fmaxf(a, 0.0f);
    b = fmaxf(b, 0.0f);
    return pack2(a, b);
}

#define HID 64

// Shared layout per hidden unit j: 5 ulonglong2 (80 bytes, 16B-aligned):
//  [0] = (dup W1f[0][j], dup W1f[1][j])
//  [1] = (dup W1f[2][j], dup W1f[3][j])
//  [2] = (dup W2[j][0],  dup W2[j][1])
//  [3] = (dup W2[j][2],  dup W2[j][3])
//  [4] = (dup b1f[j],    0)
__global__ void __launch_bounds__(256, 3)
mlp_kernel(const float4* __restrict__ x,
           const float* __restrict__ W1,   // [4][64]
           const float* __restrict__ b1,   // [64]
           const float* __restrict__ W2,   // [64][4]
           const float* __restrict__ b2,   // [4]
           float4* __restrict__ out,
           int rows)
{
    __shared__ ulonglong2 sW[HID * 5];

    const int t = threadIdx.x;
    if (t < HID) {
        const float lim_a[4]    = {0.001f, 0.02f, 0.05f, 0.001f};
        const float inv_span[4] = {1.0f/0.003f, 1.0f/0.03f, 1.0f/0.15f, 1.0f/0.003f};
        const int j = t;
        float w[4];
        float bf = b1[j];
        #pragma unroll
        for (int i = 0; i < 4; i++) {
            w[i] = W1[i * HID + j] * inv_span[i];
            bf -= lim_a[i] * w[i];
        }
        float v2[4];
        #pragma unroll
        for (int k = 0; k < 4; k++) v2[k] = W2[j * 4 + k];

        sW[j * 5 + 0] = make_ulonglong2(pack2(w[0], w[0]), pack2(w[1], w[1]));
        sW[j * 5 + 1] = make_ulonglong2(pack2(w[2], w[2]), pack2(w[3], w[3]));
        sW[j * 5 + 2] = make_ulonglong2(pack2(v2[0], v2[0]), pack2(v2[1], v2[1]));
        sW[j * 5 + 3] = make_ulonglong2(pack2(v2[2], v2[2]), pack2(v2[3], v2[3]));
        sW[j * 5 + 4] = make_ulonglong2(pack2(bf, bf), 0ull);
    }
    __syncthreads();

    const float bb0 = b2[0], bb1 = b2[1], bb2 = b2[2], bb3 = b2[3];
    const float lim_a_k[4] = {0.001f, 0.02f, 0.05f, 0.001f};
    const float span_k[4]  = {0.003f, 0.03f, 0.15f, 0.003f};

    const int tid     = blockIdx.x * blockDim.x + threadIdx.x;
    const int gstride = gridDim.x * blockDim.x * 4;

    for (int r = tid * 4; r < rows; r += gstride) {
        // ---- load 4 rows (clamped only on ragged tail) ----
        float4 xr[4];
        if (r + 3 < rows) {
            #pragma unroll
            for (int i = 0; i < 4; i++) xr[i] = x[r + i];
        } else {
            #pragma unroll
            for (int i = 0; i < 4; i++) {
                int ri = r + i;
                xr[i] = x[ri < rows ? ri : (rows - 1)];
            }
        }

        // pack row-pairs as u64: xp[pr][i] = (x_i(row 2pr), x_i(row 2pr+1))
        u64 xp[2][4];
        #pragma unroll
        for (int pr = 0; pr < 2; pr++) {
            xp[pr][0] = pack2(xr[2*pr].x, xr[2*pr+1].x);
            xp[pr][1] = pack2(xr[2*pr].y, xr[2*pr+1].y);
            xp[pr][2] = pack2(xr[2*pr].z, xr[2*pr+1].z);
            xp[pr][3] = pack2(xr[2*pr].w, xr[2*pr+1].w);
        }

        // output accumulators (init with bias, dup'd across the pair)
        u64 y[2][4];
        #pragma unroll
        for (int pr = 0; pr < 2; pr++) {
            y[pr][0] = pack2(bb0, bb0);
            y[pr][1] = pack2(bb1, bb1);
            y[pr][2] = pack2(bb2, bb2);
            y[pr][3] = pack2(bb3, bb3);
        }

        // ---- fused layer1 + relu + layer2 over 64 hidden units ----
        #pragma unroll 8
        for (int j = 0; j < HID; j++) {
            const ulonglong2 wA = sW[j * 5 + 0];  // w1d0, w1d1
            const ulonglong2 wB = sW[j * 5 + 1];  // w1d2, w1d3
            const ulonglong2 wC = sW[j * 5 + 2];  // w2d0, w2d1
            const ulonglong2 wD = sW[j * 5 + 3];  // w2d2, w2d3
            const u64 b1d = sW[j * 5 + 4].x;

            #pragma unroll
            for (int pr = 0; pr < 2; pr++) {
                u64 h = ffma2(xp[pr][0], wA.x, b1d);
                h = ffma2(xp[pr][1], wA.y, h);
                h = ffma2(xp[pr][2], wB.x, h);
                h = ffma2(xp[pr][3], wB.y, h);
                h = relu2(h);
                y[pr][0] = ffma2(h, wC.x, y[pr][0]);
                y[pr][1] = ffma2(h, wC.y, y[pr][1]);
                y[pr][2] = ffma2(h, wD.x, y[pr][2]);
                y[pr][3] = ffma2(h, wD.y, y[pr][3]);
            }
        }

        // ---- sigmoid epilogue + store ----
        #pragma unroll
        for (int pr = 0; pr < 2; pr++) {
            float4 o0, o1;
            float* p0 = &o0.x;
            float* p1 = &o1.x;
            #pragma unroll
            for (int k = 0; k < 4; k++) {
                float ya, yb;
                unpack2(y[pr][k], ya, yb);
                float s0 = __fdividef(1.0f, 1.0f + __expf(-ya));
                float s1 = __fdividef(1.0f, 1.0f + __expf(-yb));
                p0[k] = fmaf(span_k[k], s0, lim_a_k[k]);
                p1[k] = fmaf(span_k[k], s1, lim_a_k[k]);
            }
            int r0 = r + 2 * pr;
            if (r0 < rows)     out[r0]     = o0;
            if (r0 + 1 < rows) out[r0 + 1] = o1;
        }
    }
}

extern "C" void kernel_launch(void* const* d_in, const int* in_sizes, int n_in,
                              void* d_out, int out_size) {
    const float* x  = (const float*)d_in[0];
    const float* W1 = (const float*)d_in[1];
    const float* b1 = (const float*)d_in[2];
    const float* W2 = (const float*)d_in[3];
    const float* b2 = (const float*)d_in[4];
    const int rows = in_sizes[0] / 4;

    const int threads = 256;
    const int blocks = (rows + threads * 4 - 1) / (threads * 4);
    mlp_kernel<<<blocks, threads>>>(
        (const float4*)x, W1, b1, W2, b2, (float4*)d_out, rows);
}

// round 4
// speedup vs baseline: 1.3946x; 1.3946x over previous
#include <cuda_runtime.h>

// Net_90434831385322: z = LIM_A + span*sigmoid( relu(((x-LIM_A)/span) @ W1 + b1) @ W2 + b2 )
//
// R4 design:
//  - Input scaling folded into W1/b1; layer2 fused (no h[] array).
//  - f32x2 packed math, u64 registers end-to-end; weights pre-duplicated in smem.
//  - 8 rows/thread (4 row-pairs) to amortize the 320 LDS of the j-sweep.
//  - Warp-interleaved row assignment: row = warpBase + lane + 32*i  -> every
//    LDG.128/STG.128 warp instruction touches 4 cache lines, not 32.

typedef unsigned long long u64;

__device__ __forceinline__ u64 ffma2(u64 a, u64 b, u64 c) {
    u64 d;
    asm("fma.rn.f32x2 %0, %1, %2, %3;" : "=l"(d) : "l"(a), "l"(b), "l"(c));
    return d;
}
__device__ __forceinline__ u64 pack2(float lo, float hi) {
    u64 d;
    asm("mov.b64 %0, {%1, %2};" : "=l"(d) : "f"(lo), "f"(hi));
    return d;
}
__device__ __forceinline__ void unpack2(u64 v, float& lo, float& hi) {
    asm("mov.b64 {%0, %1}, %2;" : "=f"(lo), "=f"(hi) : "l"(v));
}
__device__ __forceinline__ u64 relu2(u64 h) {
    float a, b;
    unpack2(h, a, b);
    a = fmaxf(a, 0.0f);
    b = fmaxf(b, 0.0f);
    return pack2(a, b);
}

#define HID 64
#define NPR 4              // row-pairs per thread (8 rows)
#define ROWS_PER_WARP 256  // 32 lanes * 8 rows

// Shared: 5 ulonglong2 per hidden unit j:
//  [0]=(dupW1f0, dupW1f1) [1]=(dupW1f2, dupW1f3)
//  [2]=(dupW2_0, dupW2_1) [3]=(dupW2_2, dupW2_3) [4]=(dupB1f, 0)
__global__ void __launch_bounds__(256, 2)
mlp_kernel(const float4* __restrict__ x,
           const float* __restrict__ W1,   // [4][64]
           const float* __restrict__ b1,   // [64]
           const float* __restrict__ W2,   // [64][4]
           const float* __restrict__ b2,   // [4]
           float4* __restrict__ out,
           int rows)
{
    __shared__ ulonglong2 sW[HID * 5];

    const int t = threadIdx.x;
    if (t < HID) {
        const float lim_a[4]    = {0.001f, 0.02f, 0.05f, 0.001f};
        const float inv_span[4] = {1.0f/0.003f, 1.0f/0.03f, 1.0f/0.15f, 1.0f/0.003f};
        const int j = t;
        float w[4];
        float bf = b1[j];
        #pragma unroll
        for (int i = 0; i < 4; i++) {
            w[i] = W1[i * HID + j] * inv_span[i];
            bf -= lim_a[i] * w[i];
        }
        float v2[4];
        #pragma unroll
        for (int k = 0; k < 4; k++) v2[k] = W2[j * 4 + k];

        sW[j * 5 + 0] = make_ulonglong2(pack2(w[0], w[0]), pack2(w[1], w[1]));
        sW[j * 5 + 1] = make_ulonglong2(pack2(w[2], w[2]), pack2(w[3], w[3]));
        sW[j * 5 + 2] = make_ulonglong2(pack2(v2[0], v2[0]), pack2(v2[1], v2[1]));
        sW[j * 5 + 3] = make_ulonglong2(pack2(v2[2], v2[2]), pack2(v2[3], v2[3]));
        sW[j * 5 + 4] = make_ulonglong2(pack2(bf, bf), 0ull);
    }
    __syncthreads();

    const float bb0 = b2[0], bb1 = b2[1], bb2 = b2[2], bb3 = b2[3];
    const float lim_a_k[4] = {0.001f, 0.02f, 0.05f, 0.001f};
    const float span_k[4]  = {0.003f, 0.03f, 0.15f, 0.003f};

    const int lane = t & 31;
    const int warp = t >> 5;
    const int warpsPerBlock = blockDim.x >> 5;
    // Each warp owns 256 consecutive rows; thread handles rows base + 32*i.
    const int base = (blockIdx.x * warpsPerBlock + warp) * ROWS_PER_WARP + lane;

    const bool full = (base + 32 * (2 * NPR - 1)) < rows;

    // ---- load 8 rows, pack row-pairs as u64 ----
    u64 xp[NPR][4];
    #pragma unroll
    for (int pr = 0; pr < NPR; pr++) {
        int r0 = base + 32 * (2 * pr);
        int r1 = base + 32 * (2 * pr + 1);
        if (!full) {
            r0 = r0 < rows ? r0 : (rows - 1);
            r1 = r1 < rows ? r1 : (rows - 1);
        }
        const float4 a = x[r0];
        const float4 b = x[r1];
        xp[pr][0] = pack2(a.x, b.x);
        xp[pr][1] = pack2(a.y, b.y);
        xp[pr][2] = pack2(a.z, b.z);
        xp[pr][3] = pack2(a.w, b.w);
    }

    // ---- accumulators ----
    u64 y[NPR][4];
    #pragma unroll
    for (int pr = 0; pr < NPR; pr++) {
        y[pr][0] = pack2(bb0, bb0);
        y[pr][1] = pack2(bb1, bb1);
        y[pr][2] = pack2(bb2, bb2);
        y[pr][3] = pack2(bb3, bb3);
    }

    // ---- fused layer1 + relu + layer2 over 64 hidden units ----
    #pragma unroll 16
    for (int j = 0; j < HID; j++) {
        const ulonglong2 wA = sW[j * 5 + 0];
        const ulonglong2 wB = sW[j * 5 + 1];
        const ulonglong2 wC = sW[j * 5 + 2];
        const ulonglong2 wD = sW[j * 5 + 3];
        const u64 b1d = sW[j * 5 + 4].x;

        #pragma unroll
        for (int pr = 0; pr < NPR; pr++) {
            u64 h = ffma2(xp[pr][0], wA.x, b1d);
            h = ffma2(xp[pr][1], wA.y, h);
            h = ffma2(xp[pr][2], wB.x, h);
            h = ffma2(xp[pr][3], wB.y, h);
            h = relu2(h);
            y[pr][0] = ffma2(h, wC.x, y[pr][0]);
            y[pr][1] = ffma2(h, wC.y, y[pr][1]);
            y[pr][2] = ffma2(h, wD.x, y[pr][2]);
            y[pr][3] = ffma2(h, wD.y, y[pr][3]);
        }
    }

    // ---- sigmoid epilogue + coalesced stores ----
    #pragma unroll
    for (int pr = 0; pr < NPR; pr++) {
        float4 o0, o1;
        float* p0 = &o0.x;
        float* p1 = &o1.x;
        #pragma unroll
        for (int k = 0; k < 4; k++) {
            float ya, yb;
            unpack2(y[pr][k], ya, yb);
            const float s0 = __fdividef(1.0f, 1.0f + __expf(-ya));
            const float s1 = __fdividef(1.0f, 1.0f + __expf(-yb));
            p0[k] = fmaf(span_k[k], s0, lim_a_k[k]);
            p1[k] = fmaf(span_k[k], s1, lim_a_k[k]);
        }
        const int r0 = base + 32 * (2 * pr);
        const int r1 = base + 32 * (2 * pr + 1);
        if (full) {
            out[r0] = o0;
            out[r1] = o1;
        } else {
            if (r0 < rows) out[r0] = o0;
            if (r1 < rows) out[r1] = o1;
        }
    }
}

extern "C" void kernel_launch(void* const* d_in, const int* in_sizes, int n_in,
                              void* d_out, int out_size) {
    const float* x  = (const float*)d_in[0];
    const float* W1 = (const float*)d_in[1];
    const float* b1 = (const float*)d_in[2];
    const float* W2 = (const float*)d_in[3];
    const float* b2 = (const float*)d_in[4];
    const int rows = in_sizes[0] / 4;

    const int threads = 256;
    const int rowsPerBlock = (threads / 32) * ROWS_PER_WARP;  // 2048
    const int blocks = (rows + rowsPerBlock - 1) / rowsPerBlock;
    mlp_kernel<<<blocks, threads>>>(
        (const float4*)x, W1, b1, W2, b2, (float4*)d_out, rows);
}

// round 5
// speedup vs baseline: 1.4059x; 1.0081x over previous
#include <cuda_runtime.h>

// Net_90434831385322: z = LIM_A + span*sigmoid( relu(((x-LIM_A)/span) @ W1 + b1) @ W2 + b2 )
//
// R5 design:
//  - Same fused f32x2 scheme as R4 (fold scaling into W1/b1, fuse layer2,
//    pre-duplicated u64 weights in smem, warp-interleaved coalesced rows).
//  - NPR=3 (6 rows/thread) + __launch_bounds__(256,3): regs <=84 -> 24 warps/SM
//    (was 16). Per-row fma work unchanged; 50% more warps to fill the 40% of
//    fma-pipe cycles R4 left idle.

typedef unsigned long long u64;

__device__ __forceinline__ u64 ffma2(u64 a, u64 b, u64 c) {
    u64 d;
    asm("fma.rn.f32x2 %0, %1, %2, %3;" : "=l"(d) : "l"(a), "l"(b), "l"(c));
    return d;
}
__device__ __forceinline__ u64 pack2(float lo, float hi) {
    u64 d;
    asm("mov.b64 %0, {%1, %2};" : "=l"(d) : "f"(lo), "f"(hi));
    return d;
}
__device__ __forceinline__ void unpack2(u64 v, float& lo, float& hi) {
    asm("mov.b64 {%0, %1}, %2;" : "=f"(lo), "=f"(hi) : "l"(v));
}
__device__ __forceinline__ u64 relu2(u64 h) {
    float a, b;
    unpack2(h, a, b);
    a = fmaxf(a, 0.0f);
    b = fmaxf(b, 0.0f);
    return pack2(a, b);
}

#define HID 64
#define NPR 3              // row-pairs per thread (6 rows)
#define ROWS_PER_WARP 192  // 32 lanes * 6 rows

__global__ void __launch_bounds__(256, 3)
mlp_kernel(const float4* __restrict__ x,
           const float* __restrict__ W1,   // [4][64]
           const float* __restrict__ b1,   // [64]
           const float* __restrict__ W2,   // [64][4]
           const float* __restrict__ b2,   // [4]
           float4* __restrict__ out,
           int rows)
{
    __shared__ ulonglong2 sW[HID * 5];

    const int t = threadIdx.x;
    if (t < HID) {
        const float lim_a[4]    = {0.001f, 0.02f, 0.05f, 0.001f};
        const float inv_span[4] = {1.0f/0.003f, 1.0f/0.03f, 1.0f/0.15f, 1.0f/0.003f};
        const int j = t;
        float w[4];
        float bf = b1[j];
        #pragma unroll
        for (int i = 0; i < 4; i++) {
            w[i] = W1[i * HID + j] * inv_span[i];
            bf -= lim_a[i] * w[i];
        }
        float v2[4];
        #pragma unroll
        for (int k = 0; k < 4; k++) v2[k] = W2[j * 4 + k];

        sW[j * 5 + 0] = make_ulonglong2(pack2(w[0], w[0]), pack2(w[1], w[1]));
        sW[j * 5 + 1] = make_ulonglong2(pack2(w[2], w[2]), pack2(w[3], w[3]));
        sW[j * 5 + 2] = make_ulonglong2(pack2(v2[0], v2[0]), pack2(v2[1], v2[1]));
        sW[j * 5 + 3] = make_ulonglong2(pack2(v2[2], v2[2]), pack2(v2[3], v2[3]));
        sW[j * 5 + 4] = make_ulonglong2(pack2(bf, bf), 0ull);
    }
    __syncthreads();

    const float bb0 = b2[0], bb1 = b2[1], bb2 = b2[2], bb3 = b2[3];
    const float lim_a_k[4] = {0.001f, 0.02f, 0.05f, 0.001f};
    const float span_k[4]  = {0.003f, 0.03f, 0.15f, 0.003f};

    const int lane = t & 31;
    const int warp = t >> 5;
    const int warpsPerBlock = blockDim.x >> 5;
    const int base = (blockIdx.x * warpsPerBlock + warp) * ROWS_PER_WARP + lane;

    const bool full = (base + 32 * (2 * NPR - 1)) < rows;

    // ---- load 6 rows, pack row-pairs as u64 ----
    u64 xp[NPR][4];
    #pragma unroll
    for (int pr = 0; pr < NPR; pr++) {
        int r0 = base + 32 * (2 * pr);
        int r1 = base + 32 * (2 * pr + 1);
        if (!full) {
            r0 = r0 < rows ? r0 : (rows - 1);
            r1 = r1 < rows ? r1 : (rows - 1);
        }
        const float4 a = x[r0];
        const float4 b = x[r1];
        xp[pr][0] = pack2(a.x, b.x);
        xp[pr][1] = pack2(a.y, b.y);
        xp[pr][2] = pack2(a.z, b.z);
        xp[pr][3] = pack2(a.w, b.w);
    }

    // ---- accumulators ----
    u64 y[NPR][4];
    #pragma unroll
    for (int pr = 0; pr < NPR; pr++) {
        y[pr][0] = pack2(bb0, bb0);
        y[pr][1] = pack2(bb1, bb1);
        y[pr][2] = pack2(bb2, bb2);
        y[pr][3] = pack2(bb3, bb3);
    }

    // ---- fused layer1 + relu + layer2 over 64 hidden units ----
    #pragma unroll 16
    for (int j = 0; j < HID; j++) {
        const ulonglong2 wA = sW[j * 5 + 0];
        const ulonglong2 wB = sW[j * 5 + 1];
        const ulonglong2 wC = sW[j * 5 + 2];
        const ulonglong2 wD = sW[j * 5 + 3];
        const u64 b1d = sW[j * 5 + 4].x;

        #pragma unroll
        for (int pr = 0; pr < NPR; pr++) {
            u64 h = ffma2(xp[pr][0], wA.x, b1d);
            h = ffma2(xp[pr][1], wA.y, h);
            h = ffma2(xp[pr][2], wB.x, h);
            h = ffma2(xp[pr][3], wB.y, h);
            h = relu2(h);
            y[pr][0] = ffma2(h, wC.x, y[pr][0]);
            y[pr][1] = ffma2(h, wC.y, y[pr][1]);
            y[pr][2] = ffma2(h, wD.x, y[pr][2]);
            y[pr][3] = ffma2(h, wD.y, y[pr][3]);
        }
    }

    // ---- sigmoid epilogue + coalesced stores ----
    #pragma unroll
    for (int pr = 0; pr < NPR; pr++) {
        float4 o0, o1;
        float* p0 = &o0.x;
        float* p1 = &o1.x;
        #pragma unroll
        for (int k = 0; k < 4; k++) {
            float ya, yb;
            unpack2(y[pr][k], ya, yb);
            const float s0 = __fdividef(1.0f, 1.0f + __expf(-ya));
            const float s1 = __fdividef(1.0f, 1.0f + __expf(-yb));
            p0[k] = fmaf(span_k[k], s0, lim_a_k[k]);
            p1[k] = fmaf(span_k[k], s1, lim_a_k[k]);
        }
        const int r0 = base + 32 * (2 * pr);
        const int r1 = base + 32 * (2 * pr + 1);
        if (full) {
            out[r0] = o0;
            out[r1] = o1;
        } else {
            if (r0 < rows) out[r0] = o0;
            if (r1 < rows) out[r1] = o1;
        }
    }
}

extern "C" void kernel_launch(void* const* d_in, const int* in_sizes, int n_in,
                              void* d_out, int out_size) {
    const float* x  = (const float*)d_in[0];
    const float* W1 = (const float*)d_in[1];
    const float* b1 = (const float*)d_in[2];
    const float* W2 = (const float*)d_in[3];
    const float* b2 = (const float*)d_in[4];
    const int rows = in_sizes[0] / 4;

    const int threads = 256;
    const int rowsPerBlock = (threads / 32) * ROWS_PER_WARP;  // 1536
    const int blocks = (rows + rowsPerBlock - 1) / rowsPerBlock;
    mlp_kernel<<<blocks, threads>>>(
        (const float4*)x, W1, b1, W2, b2, (float4*)d_out, rows);
}